// round 8
// baseline (speedup 1.0000x reference)
#include <cuda_runtime.h>
#include <math_constants.h>

static constexpr int NPTS  = 4096;
static constexpr int NUP   = 16384;
static constexpr int BATCH = 4;
static constexpr int C     = 64;

static constexpr int S      = 4;            // point slices (measured best)
static constexpr int SLICE  = NPTS / S;     // 1024 points
static constexpr int TPB_A  = 128;
static constexpr int QA     = 2;            // queries per thread (phase A)
static constexpr int QTILE  = TPB_A * QA;   // 256 queries per block
static constexpr int TPB_B  = 256;

__constant__ __align__(16) float cW[C * C];
__constant__ __align__(16) float cB[C];

// per-(slice, batch, query) top-3: values and indices (bitcast)
__device__ float4 g_scrV[S * BATCH * NUP];
__device__ float4 g_scrI[S * BATCH * NUP];

// ---- packed f32x2 helpers (Blackwell) ----
__device__ __forceinline__ unsigned long long pk2(float lo, float hi) {
    unsigned long long r;
    asm("mov.b64 %0, {%1, %2};" : "=l"(r) : "f"(lo), "f"(hi));
    return r;
}
__device__ __forceinline__ unsigned long long fma2(unsigned long long a,
                                                   unsigned long long b,
                                                   unsigned long long c) {
    unsigned long long d;
    asm("fma.rn.f32x2 %0, %1, %2, %3;" : "=l"(d) : "l"(a), "l"(b), "l"(c));
    return d;
}
__device__ __forceinline__ void unpk2(unsigned long long v, float& lo, float& hi) {
    asm("mov.b64 {%0, %1}, %2;" : "=f"(lo), "=f"(hi) : "l"(v));
}

// strict-< branchy insert (used in cheap merge path only)
__device__ __forceinline__ void ins3(float v, int i,
                                     float& v0, float& v1, float& v2,
                                     int& i0, int& i1, int& i2) {
    if (v < v2) {
        if (v < v1) {
            v2 = v1; i2 = i1;
            if (v < v0) { v1 = v0; i1 = i0; v0 = v; i0 = i; }
            else        { v1 = v;  i1 = i; }
        } else { v2 = v; i2 = i; }
    }
}

// branchless strict-< insert: flat select network, no nested divergence.
// Ties keep the incumbent (earlier index) — matches jax.lax.top_k stability.
__device__ __forceinline__ void ins3_flat(float s, int j,
                                          float& v0, float& v1, float& v2,
                                          int& i0, int& i1, int& i2) {
    const bool p0 = s < v0;
    const bool p1 = s < v1;
    const bool p2 = s < v2;
    v2 = p1 ? v1 : (p2 ? s : v2);
    i2 = p1 ? i1 : (p2 ? j : i2);
    v1 = p0 ? v0 : (p1 ? s : v1);
    i1 = p0 ? i0 : (p1 ? j : i1);
    v0 = p0 ? s : v0;
    i0 = p0 ? j : i0;
}

// ============ Phase A: per-slice top-3, points pair-packed as u64 lanes ======
__global__ void __launch_bounds__(TPB_A, 8)
knn_slice_kernel(const float* __restrict__ pos,
                 const float* __restrict__ pos_up)
{
    // pair p: [2p] = {(x0,x1),(y0,y1)}, [2p+1] = {(z0,z1),(h0,h1)}
    __shared__ ulonglong2 spair[SLICE];

    const int s   = blockIdx.y;
    const int b   = blockIdx.z;
    const int tid = threadIdx.x;

    {
        const float* pb = pos + ((size_t)b * NPTS + (size_t)s * SLICE) * 3;
        for (int p = tid; p < SLICE / 2; p += TPB_A) {
            const float* s6 = pb + 6 * p;
            float x0 = s6[0], y0 = s6[1], z0 = s6[2];
            float x1 = s6[3], y1 = s6[4], z1 = s6[5];
            ulonglong2 A, B;
            A.x = pk2(x0, x1);
            A.y = pk2(y0, y1);
            B.x = pk2(z0, z1);
            B.y = pk2(0.5f * (x0 * x0 + y0 * y0 + z0 * z0),
                      0.5f * (x1 * x1 + y1 * y1 + z1 * z1));
            spair[2 * p + 0] = A;
            spair[2 * p + 1] = B;
        }
    }
    __syncthreads();

    const int qbase = blockIdx.x * QTILE + tid;

    unsigned long long nx[QA], ny[QA], nz[QA];
    #pragma unroll
    for (int k = 0; k < QA; ++k) {
        const int q = qbase + k * TPB_A;
        const float* pu = pos_up + (size_t)(b * NUP + q) * 3;
        float x = pu[0], y = pu[1], z = pu[2];
        nx[k] = pk2(-x, -x); ny[k] = pk2(-y, -y); nz[k] = pk2(-z, -z);
    }

    float v0[QA], v1[QA], v2[QA];
    int   i0[QA], i1[QA], i2[QA];
    #pragma unroll
    for (int k = 0; k < QA; ++k) {
        v0[k] = v1[k] = v2[k] = CUDART_INF_F;
        i0[k] = i1[k] = i2[k] = 0;
    }

    const int jbase = s * SLICE;

    #pragma unroll 4
    for (int p = 0; p < SLICE / 2; ++p) {
        ulonglong2 A  = spair[2 * p + 0];   // xs, ys (packed point-pairs)
        ulonglong2 Bv = spair[2 * p + 1];   // zs, hs

        #pragma unroll
        for (int k = 0; k < QA; ++k) {
            unsigned long long sP = fma2(A.x, nx[k], Bv.y);
            sP = fma2(A.y, ny[k], sP);
            sP = fma2(Bv.x, nz[k], sP);
            float s0, s1;
            unpk2(sP, s0, s1);
            if (fminf(s0, s1) < v2[k]) {     // per-query gate; FLAT body below
                ins3_flat(s0, jbase + 2 * p,     v0[k], v1[k], v2[k], i0[k], i1[k], i2[k]);
                ins3_flat(s1, jbase + 2 * p + 1, v0[k], v1[k], v2[k], i0[k], i1[k], i2[k]);
            }
        }
    }

    #pragma unroll
    for (int k = 0; k < QA; ++k) {
        const int q = qbase + k * TPB_A;
        const size_t o = ((size_t)s * BATCH + b) * NUP + q;
        g_scrV[o] = make_float4(v0[k], v1[k], v2[k], 0.0f);
        g_scrI[o] = make_float4(__int_as_float(i0[k]), __int_as_float(i1[k]),
                                __int_as_float(i2[k]), 0.0f);
    }
}

// ====== Phase B: merge + interp + f32x2 GEMM (W via LDC.128) ================
__global__ void __launch_bounds__(TPB_B, 2)
epilogue_kernel(const float* __restrict__ feature,
                const float* __restrict__ pos_up,
                float* __restrict__ out)
{
    const int b = blockIdx.y;
    const int q = blockIdx.x * TPB_B + threadIdx.x;

    // merge S slice-top-3s (ascending slice order, strict < => global stability)
    float v0 = CUDART_INF_F, v1 = CUDART_INF_F, v2 = CUDART_INF_F;
    int   i0 = 0, i1 = 0, i2 = 0;
    #pragma unroll
    for (int s = 0; s < S; ++s) {
        const size_t o = ((size_t)s * BATCH + b) * NUP + q;
        float4 vv = g_scrV[o];
        float4 ii = g_scrI[o];
        ins3(vv.x, __float_as_int(ii.x), v0, v1, v2, i0, i1, i2);
        ins3(vv.y, __float_as_int(ii.y), v0, v1, v2, i0, i1, i2);
        ins3(vv.z, __float_as_int(ii.z), v0, v1, v2, i0, i1, i2);
    }

    const float* pu = pos_up + (size_t)(b * NUP + q) * 3;
    const float pux = pu[0], puy = pu[1], puz = pu[2];
    const float nu  = pux * pux + puy * puy + puz * puz;

    float w0 = 1.0f / (__fmaf_rn(2.0f, v0, nu) + 1e-6f);
    float w1 = 1.0f / (__fmaf_rn(2.0f, v1, nu) + 1e-6f);
    float w2 = 1.0f / (__fmaf_rn(2.0f, v2, nu) + 1e-6f);
    float inv = 1.0f / (w0 + w1 + w2);
    w0 *= inv; w1 *= inv; w2 *= inv;

    const float4* f0 = reinterpret_cast<const float4*>(feature + (size_t)(b * NPTS + i0) * C);
    const float4* f1 = reinterpret_cast<const float4*>(feature + (size_t)(b * NPTS + i1) * C);
    const float4* f2 = reinterpret_cast<const float4*>(feature + (size_t)(b * NPTS + i2) * C);

    // W and bias as 16B-vector constant loads (LDC.128), math as f32x2
    const ulonglong2* cW2v = reinterpret_cast<const ulonglong2*>(cW);
    const ulonglong2* cB2v = reinterpret_cast<const ulonglong2*>(cB);

    unsigned long long acc2[32];     // 32 packed d-pairs
    #pragma unroll
    for (int t = 0; t < 16; ++t) {
        ulonglong2 bb = cB2v[t];
        acc2[2 * t + 0] = bb.x;
        acc2[2 * t + 1] = bb.y;
    }

    #pragma unroll 4
    for (int c4 = 0; c4 < 16; ++c4) {
        float4 a = __ldg(f0 + c4);
        float4 e = __ldg(f1 + c4);
        float4 g = __ldg(f2 + c4);
        float nf[4];
        nf[0] = __fmaf_rn(w0, a.x, __fmaf_rn(w1, e.x, w2 * g.x));
        nf[1] = __fmaf_rn(w0, a.y, __fmaf_rn(w1, e.y, w2 * g.y));
        nf[2] = __fmaf_rn(w0, a.z, __fmaf_rn(w1, e.z, w2 * g.z));
        nf[3] = __fmaf_rn(w0, a.w, __fmaf_rn(w1, e.w, w2 * g.w));

        #pragma unroll
        for (int kk = 0; kk < 4; ++kk) {
            const unsigned long long nf2 = pk2(nf[kk], nf[kk]);   // broadcast pack
            const ulonglong2* wr = cW2v + (size_t)(4 * c4 + kk) * 16;
            #pragma unroll
            for (int t = 0; t < 16; ++t) {
                ulonglong2 wv = wr[t];                            // LDC.128
                acc2[2 * t + 0] = fma2(nf2, wv.x, acc2[2 * t + 0]);
                acc2[2 * t + 1] = fma2(nf2, wv.y, acc2[2 * t + 1]);
            }
        }
    }

    // ReLU on unpacked halves + vectorized store
    float4* o4 = reinterpret_cast<float4*>(out + (size_t)(b * NUP + q) * C);
    #pragma unroll
    for (int m = 0; m < 16; ++m) {
        float x0, x1, x2, x3;
        unpk2(acc2[2 * m + 0], x0, x1);
        unpk2(acc2[2 * m + 1], x2, x3);
        float4 v;
        v.x = fmaxf(x0, 0.0f);
        v.y = fmaxf(x1, 0.0f);
        v.z = fmaxf(x2, 0.0f);
        v.w = fmaxf(x3, 0.0f);
        o4[m] = v;
    }
}

extern "C" void kernel_launch(void* const* d_in, const int* in_sizes, int n_in,
                              void* d_out, int out_size)
{
    const float* feature = (const float*)d_in[0];
    const float* pos     = (const float*)d_in[1];
    const float* pos_up  = (const float*)d_in[2];
    const float* W       = (const float*)d_in[3];
    const float* bias    = (const float*)d_in[4];
    float* out = (float*)d_out;

    cudaMemcpyToSymbolAsync(cW, W,    C * C * sizeof(float), 0, cudaMemcpyDeviceToDevice, 0);
    cudaMemcpyToSymbolAsync(cB, bias, C * sizeof(float),     0, cudaMemcpyDeviceToDevice, 0);

    dim3 gridA(NUP / QTILE, S, BATCH);      // (64, 4, 4) = 1024 blocks
    knn_slice_kernel<<<gridA, TPB_A>>>(pos, pos_up);

    dim3 gridB(NUP / TPB_B, BATCH);         // (64, 4) = 256 blocks
    epilogue_kernel<<<gridB, TPB_B>>>(feature, pos_up, out);
}

// round 9
// speedup vs baseline: 1.0134x; 1.0134x over previous
#include <cuda_runtime.h>
#include <math_constants.h>

static constexpr int NPTS  = 4096;
static constexpr int NUP   = 16384;
static constexpr int BATCH = 4;
static constexpr int C     = 64;

static constexpr int S      = 4;            // point slices (measured best)
static constexpr int SLICE  = NPTS / S;     // 1024 points
static constexpr int TPB_A  = 128;
static constexpr int QA     = 2;            // queries per thread (phase A)
static constexpr int QTILE  = TPB_A * QA;   // 256 queries per block
static constexpr int TPB_B  = 256;          // 64 queries x 4 d-quarters

__constant__ __align__(16) float cW[C * C];
__constant__ __align__(16) float cB[C];

// per-(slice, batch, query) top-3: values and indices (bitcast)
__device__ float4 g_scrV[S * BATCH * NUP];
__device__ float4 g_scrI[S * BATCH * NUP];

// ---- packed f32x2 helpers (Blackwell) ----
__device__ __forceinline__ unsigned long long pk2(float lo, float hi) {
    unsigned long long r;
    asm("mov.b64 %0, {%1, %2};" : "=l"(r) : "f"(lo), "f"(hi));
    return r;
}
__device__ __forceinline__ unsigned long long fma2(unsigned long long a,
                                                   unsigned long long b,
                                                   unsigned long long c) {
    unsigned long long d;
    asm("fma.rn.f32x2 %0, %1, %2, %3;" : "=l"(d) : "l"(a), "l"(b), "l"(c));
    return d;
}
__device__ __forceinline__ void unpk2(unsigned long long v, float& lo, float& hi) {
    asm("mov.b64 {%0, %1}, %2;" : "=f"(lo), "=f"(hi) : "l"(v));
}

// strict-< branchy insert: keeps earliest index on ties (jax.lax.top_k stability)
__device__ __forceinline__ void ins3(float v, int i,
                                     float& v0, float& v1, float& v2,
                                     int& i0, int& i1, int& i2) {
    if (v < v2) {
        if (v < v1) {
            v2 = v1; i2 = i1;
            if (v < v0) { v1 = v0; i1 = i0; v0 = v; i0 = i; }
            else        { v1 = v;  i1 = i; }
        } else { v2 = v; i2 = i; }
    }
}

// ============ Phase A: per-slice top-3, points pair-packed as u64 lanes ======
__global__ void __launch_bounds__(TPB_A, 8)
knn_slice_kernel(const float* __restrict__ pos,
                 const float* __restrict__ pos_up)
{
    // pair p: [2p] = {(x0,x1),(y0,y1)}, [2p+1] = {(z0,z1),(h0,h1)}
    __shared__ ulonglong2 spair[SLICE];

    const int s   = blockIdx.y;
    const int b   = blockIdx.z;
    const int tid = threadIdx.x;

    {
        const float* pb = pos + ((size_t)b * NPTS + (size_t)s * SLICE) * 3;
        for (int p = tid; p < SLICE / 2; p += TPB_A) {
            const float* s6 = pb + 6 * p;
            float x0 = s6[0], y0 = s6[1], z0 = s6[2];
            float x1 = s6[3], y1 = s6[4], z1 = s6[5];
            ulonglong2 A, B;
            A.x = pk2(x0, x1);
            A.y = pk2(y0, y1);
            B.x = pk2(z0, z1);
            B.y = pk2(0.5f * (x0 * x0 + y0 * y0 + z0 * z0),
                      0.5f * (x1 * x1 + y1 * y1 + z1 * z1));
            spair[2 * p + 0] = A;
            spair[2 * p + 1] = B;
        }
    }
    __syncthreads();

    const int qbase = blockIdx.x * QTILE + tid;

    unsigned long long nx[QA], ny[QA], nz[QA];
    #pragma unroll
    for (int k = 0; k < QA; ++k) {
        const int q = qbase + k * TPB_A;
        const float* pu = pos_up + (size_t)(b * NUP + q) * 3;
        float x = pu[0], y = pu[1], z = pu[2];
        nx[k] = pk2(-x, -x); ny[k] = pk2(-y, -y); nz[k] = pk2(-z, -z);
    }

    float v0[QA], v1[QA], v2[QA];
    int   i0[QA], i1[QA], i2[QA];
    #pragma unroll
    for (int k = 0; k < QA; ++k) {
        v0[k] = v1[k] = v2[k] = CUDART_INF_F;
        i0[k] = i1[k] = i2[k] = 0;
    }

    const int jbase = s * SLICE;

    #pragma unroll 4
    for (int p = 0; p < SLICE / 2; ++p) {
        ulonglong2 A  = spair[2 * p + 0];   // xs, ys (packed point-pairs)
        ulonglong2 Bv = spair[2 * p + 1];   // zs, hs

        #pragma unroll
        for (int k = 0; k < QA; ++k) {
            unsigned long long sP = fma2(A.x, nx[k], Bv.y);
            sP = fma2(A.y, ny[k], sP);
            sP = fma2(Bv.x, nz[k], sP);
            float s0, s1;
            unpk2(sP, s0, s1);
            if (fminf(s0, s1) < v2[k]) {     // per-query gate, branchy inserts
                ins3(s0, jbase + 2 * p,     v0[k], v1[k], v2[k], i0[k], i1[k], i2[k]);
                ins3(s1, jbase + 2 * p + 1, v0[k], v1[k], v2[k], i0[k], i1[k], i2[k]);
            }
        }
    }

    #pragma unroll
    for (int k = 0; k < QA; ++k) {
        const int q = qbase + k * TPB_A;
        const size_t o = ((size_t)s * BATCH + b) * NUP + q;
        g_scrV[o] = make_float4(v0[k], v1[k], v2[k], 0.0f);
        g_scrI[o] = make_float4(__int_as_float(i0[k]), __int_as_float(i1[k]),
                                __int_as_float(i2[k]), 0.0f);
    }
}

// ====== Phase B: cooperative, 4 threads per query (warp-uniform d-quarters) ==
// block = 256 thr = 8 warps = 2 query-groups(32) x 4 quarters.
// Thread computes nf for its c-quarter, shares via smem, then GEMMs its
// d-quarter (16 outputs) reading all 64 nf. All W/bias reads warp-uniform LDC.
__global__ void __launch_bounds__(TPB_B, 4)
epilogue_kernel(const float* __restrict__ feature,
                const float* __restrict__ pos_up,
                float* __restrict__ out)
{
    // nf rows padded to 68 floats (17 float4): conflict-free strided LDS.128
    __shared__ float snf[64 * 68];

    const int b       = blockIdx.y;
    const int wid     = threadIdx.x >> 5;
    const int lane    = threadIdx.x & 31;
    const int quarter = wid & 3;                      // warp-uniform
    const int qloc    = (wid >> 2) * 32 + lane;       // 0..63 within block
    const int q       = blockIdx.x * 64 + qloc;

    // ---- merge S slice-top-3s (duplicated across the 4 quarter-threads) ----
    float v0 = CUDART_INF_F, v1 = CUDART_INF_F, v2 = CUDART_INF_F;
    int   i0 = 0, i1 = 0, i2 = 0;
    #pragma unroll
    for (int s = 0; s < S; ++s) {
        const size_t o = ((size_t)s * BATCH + b) * NUP + q;
        float4 vv = g_scrV[o];
        float4 ii = g_scrI[o];
        ins3(vv.x, __float_as_int(ii.x), v0, v1, v2, i0, i1, i2);
        ins3(vv.y, __float_as_int(ii.y), v0, v1, v2, i0, i1, i2);
        ins3(vv.z, __float_as_int(ii.z), v0, v1, v2, i0, i1, i2);
    }

    const float* pu = pos_up + (size_t)(b * NUP + q) * 3;
    const float pux = pu[0], puy = pu[1], puz = pu[2];
    const float nu  = pux * pux + puy * puy + puz * puz;

    float w0 = 1.0f / (__fmaf_rn(2.0f, v0, nu) + 1e-6f);
    float w1 = 1.0f / (__fmaf_rn(2.0f, v1, nu) + 1e-6f);
    float w2 = 1.0f / (__fmaf_rn(2.0f, v2, nu) + 1e-6f);
    float inv = 1.0f / (w0 + w1 + w2);
    w0 *= inv; w1 *= inv; w2 *= inv;

    // ---- nf for this thread's c-quarter (16 channels) -> smem ----
    {
        const float4* f0 = reinterpret_cast<const float4*>(feature + (size_t)(b * NPTS + i0) * C) + quarter * 4;
        const float4* f1 = reinterpret_cast<const float4*>(feature + (size_t)(b * NPTS + i1) * C) + quarter * 4;
        const float4* f2 = reinterpret_cast<const float4*>(feature + (size_t)(b * NPTS + i2) * C) + quarter * 4;
        float4* dst = reinterpret_cast<float4*>(snf + qloc * 68 + quarter * 16);
        #pragma unroll
        for (int i = 0; i < 4; ++i) {
            float4 a = __ldg(f0 + i);
            float4 e = __ldg(f1 + i);
            float4 g = __ldg(f2 + i);
            float4 nf;
            nf.x = __fmaf_rn(w0, a.x, __fmaf_rn(w1, e.x, w2 * g.x));
            nf.y = __fmaf_rn(w0, a.y, __fmaf_rn(w1, e.y, w2 * g.y));
            nf.z = __fmaf_rn(w0, a.z, __fmaf_rn(w1, e.z, w2 * g.z));
            nf.w = __fmaf_rn(w0, a.w, __fmaf_rn(w1, e.w, w2 * g.w));
            dst[i] = nf;
        }
    }
    __syncthreads();

    // ---- GEMM: 16 outputs (d-quarter) over all 64 channels ----
    const float4* cW4 = reinterpret_cast<const float4*>(cW);
    const float4* cB4 = reinterpret_cast<const float4*>(cB);
    const float4* nfr = reinterpret_cast<const float4*>(snf + qloc * 68);

    float acc[16];
    #pragma unroll
    for (int m = 0; m < 4; ++m) {
        float4 bb = cB4[quarter * 4 + m];
        acc[4 * m + 0] = bb.x; acc[4 * m + 1] = bb.y;
        acc[4 * m + 2] = bb.z; acc[4 * m + 3] = bb.w;
    }

    #pragma unroll 4
    for (int c4 = 0; c4 < 16; ++c4) {
        float4 nf4 = nfr[c4];
        float nf[4] = {nf4.x, nf4.y, nf4.z, nf4.w};
        #pragma unroll
        for (int kk = 0; kk < 4; ++kk) {
            const float nfc = nf[kk];
            const float4* wr = cW4 + (size_t)(4 * c4 + kk) * 16 + quarter * 4;  // warp-uniform
            #pragma unroll
            for (int m = 0; m < 4; ++m) {
                float4 wv = wr[m];
                acc[4 * m + 0] = __fmaf_rn(nfc, wv.x, acc[4 * m + 0]);
                acc[4 * m + 1] = __fmaf_rn(nfc, wv.y, acc[4 * m + 1]);
                acc[4 * m + 2] = __fmaf_rn(nfc, wv.z, acc[4 * m + 2]);
                acc[4 * m + 3] = __fmaf_rn(nfc, wv.w, acc[4 * m + 3]);
            }
        }
    }

    // ---- ReLU + store this d-quarter ----
    float4* o4 = reinterpret_cast<float4*>(out + (size_t)(b * NUP + q) * C + quarter * 16);
    #pragma unroll
    for (int m = 0; m < 4; ++m) {
        float4 v;
        v.x = fmaxf(acc[4 * m + 0], 0.0f);
        v.y = fmaxf(acc[4 * m + 1], 0.0f);
        v.z = fmaxf(acc[4 * m + 2], 0.0f);
        v.w = fmaxf(acc[4 * m + 3], 0.0f);
        o4[m] = v;
    }
}

extern "C" void kernel_launch(void* const* d_in, const int* in_sizes, int n_in,
                              void* d_out, int out_size)
{
    const float* feature = (const float*)d_in[0];
    const float* pos     = (const float*)d_in[1];
    const float* pos_up  = (const float*)d_in[2];
    const float* W       = (const float*)d_in[3];
    const float* bias    = (const float*)d_in[4];
    float* out = (float*)d_out;

    cudaMemcpyToSymbolAsync(cW, W,    C * C * sizeof(float), 0, cudaMemcpyDeviceToDevice, 0);
    cudaMemcpyToSymbolAsync(cB, bias, C * sizeof(float),     0, cudaMemcpyDeviceToDevice, 0);

    dim3 gridA(NUP / QTILE, S, BATCH);      // (64, 4, 4) = 1024 blocks
    knn_slice_kernel<<<gridA, TPB_A>>>(pos, pos_up);

    dim3 gridB(NUP / 64, BATCH);            // (256, 4) = 1024 blocks
    epilogue_kernel<<<gridB, TPB_B>>>(feature, pos_up, out);
}

// round 10
// speedup vs baseline: 1.1824x; 1.1668x over previous
#include <cuda_runtime.h>
#include <math_constants.h>

static constexpr int NPTS  = 4096;
static constexpr int NUP   = 16384;
static constexpr int BATCH = 4;
static constexpr int C     = 64;

static constexpr int S      = 4;            // point slices (measured best)
static constexpr int SLICE  = NPTS / S;     // 1024 points
static constexpr int TPB_A  = 128;
static constexpr int QA     = 2;            // queries per thread (phase A)
static constexpr int QTILE  = TPB_A * QA;   // 256 queries per block
static constexpr int TPB_B  = 128;

// per-(slice, batch, query) top-3: values and indices (bitcast)
__device__ float4 g_scrV[S * BATCH * NUP];
__device__ float4 g_scrI[S * BATCH * NUP];

// ---- packed f32x2 helpers (Blackwell) ----
__device__ __forceinline__ unsigned long long pk2(float lo, float hi) {
    unsigned long long r;
    asm("mov.b64 %0, {%1, %2};" : "=l"(r) : "f"(lo), "f"(hi));
    return r;
}
__device__ __forceinline__ unsigned long long fma2(unsigned long long a,
                                                   unsigned long long b,
                                                   unsigned long long c) {
    unsigned long long d;
    asm("fma.rn.f32x2 %0, %1, %2, %3;" : "=l"(d) : "l"(a), "l"(b), "l"(c));
    return d;
}
__device__ __forceinline__ void unpk2(unsigned long long v, float& lo, float& hi) {
    asm("mov.b64 {%0, %1}, %2;" : "=f"(lo), "=f"(hi) : "l"(v));
}

// strict-< branchy insert: keeps earliest index on ties (jax.lax.top_k stability)
__device__ __forceinline__ void ins3(float v, int i,
                                     float& v0, float& v1, float& v2,
                                     int& i0, int& i1, int& i2) {
    if (v < v2) {
        if (v < v1) {
            v2 = v1; i2 = i1;
            if (v < v0) { v1 = v0; i1 = i0; v0 = v; i0 = i; }
            else        { v1 = v;  i1 = i; }
        } else { v2 = v; i2 = i; }
    }
}

// ============ Phase A: per-slice top-3, points pair-packed as u64 lanes ======
__global__ void __launch_bounds__(TPB_A, 8)
knn_slice_kernel(const float* __restrict__ pos,
                 const float* __restrict__ pos_up)
{
    // pair p: [2p] = {(x0,x1),(y0,y1)}, [2p+1] = {(z0,z1),(h0,h1)}
    __shared__ ulonglong2 spair[SLICE];

    const int s   = blockIdx.y;
    const int b   = blockIdx.z;
    const int tid = threadIdx.x;

    {
        const float* pb = pos + ((size_t)b * NPTS + (size_t)s * SLICE) * 3;
        for (int p = tid; p < SLICE / 2; p += TPB_A) {
            const float* s6 = pb + 6 * p;
            float x0 = s6[0], y0 = s6[1], z0 = s6[2];
            float x1 = s6[3], y1 = s6[4], z1 = s6[5];
            ulonglong2 A, B;
            A.x = pk2(x0, x1);
            A.y = pk2(y0, y1);
            B.x = pk2(z0, z1);
            B.y = pk2(0.5f * (x0 * x0 + y0 * y0 + z0 * z0),
                      0.5f * (x1 * x1 + y1 * y1 + z1 * z1));
            spair[2 * p + 0] = A;
            spair[2 * p + 1] = B;
        }
    }
    __syncthreads();

    const int qbase = blockIdx.x * QTILE + tid;

    unsigned long long nx[QA], ny[QA], nz[QA];
    #pragma unroll
    for (int k = 0; k < QA; ++k) {
        const int q = qbase + k * TPB_A;
        const float* pu = pos_up + (size_t)(b * NUP + q) * 3;
        float x = pu[0], y = pu[1], z = pu[2];
        nx[k] = pk2(-x, -x); ny[k] = pk2(-y, -y); nz[k] = pk2(-z, -z);
    }

    float v0[QA], v1[QA], v2[QA];
    int   i0[QA], i1[QA], i2[QA];
    #pragma unroll
    for (int k = 0; k < QA; ++k) {
        v0[k] = v1[k] = v2[k] = CUDART_INF_F;
        i0[k] = i1[k] = i2[k] = 0;
    }

    const int jbase = s * SLICE;

    #pragma unroll 4
    for (int p = 0; p < SLICE / 2; ++p) {
        ulonglong2 A  = spair[2 * p + 0];   // xs, ys (packed point-pairs)
        ulonglong2 Bv = spair[2 * p + 1];   // zs, hs

        #pragma unroll
        for (int k = 0; k < QA; ++k) {
            unsigned long long sP = fma2(A.x, nx[k], Bv.y);
            sP = fma2(A.y, ny[k], sP);
            sP = fma2(Bv.x, nz[k], sP);
            float s0, s1;
            unpk2(sP, s0, s1);
            if (fminf(s0, s1) < v2[k]) {     // per-query gate, branchy inserts
                ins3(s0, jbase + 2 * p,     v0[k], v1[k], v2[k], i0[k], i1[k], i2[k]);
                ins3(s1, jbase + 2 * p + 1, v0[k], v1[k], v2[k], i0[k], i1[k], i2[k]);
            }
        }
    }

    #pragma unroll
    for (int k = 0; k < QA; ++k) {
        const int q = qbase + k * TPB_A;
        const size_t o = ((size_t)s * BATCH + b) * NUP + q;
        g_scrV[o] = make_float4(v0[k], v1[k], v2[k], 0.0f);
        g_scrI[o] = make_float4(__int_as_float(i0[k]), __int_as_float(i1[k]),
                                __int_as_float(i2[k]), 0.0f);
    }
}

// ====== Phase B: merge + interp + GEMM with W in SHARED memory ==============
// 1 thread per query. W reads are warp-uniform LDS.128 broadcasts: pipelined
// 29-cyc latency, no constant-cache misses (the R4-R9 epilogue bottleneck).
__global__ void __launch_bounds__(TPB_B, 4)
epilogue_kernel(const float* __restrict__ feature,
                const float* __restrict__ pos_up,
                const float* __restrict__ W,
                const float* __restrict__ bias,
                float* __restrict__ out)
{
    __shared__ __align__(16) float sW[C * C];   // 16KB
    __shared__ __align__(16) float sb[C];

    const int b   = blockIdx.y;
    const int tid = threadIdx.x;
    const int q   = blockIdx.x * TPB_B + tid;

    // stage W + bias (vectorized)
    {
        const float4* Wg = reinterpret_cast<const float4*>(W);
        float4*       Ws = reinterpret_cast<float4*>(sW);
        #pragma unroll
        for (int i = tid; i < C * C / 4; i += TPB_B) Ws[i] = Wg[i];
        if (tid < C / 4)
            reinterpret_cast<float4*>(sb)[tid] = reinterpret_cast<const float4*>(bias)[tid];
    }
    __syncthreads();

    // merge S slice-top-3s (ascending slice order, strict < => global stability)
    float v0 = CUDART_INF_F, v1 = CUDART_INF_F, v2 = CUDART_INF_F;
    int   i0 = 0, i1 = 0, i2 = 0;
    #pragma unroll
    for (int s = 0; s < S; ++s) {
        const size_t o = ((size_t)s * BATCH + b) * NUP + q;
        float4 vv = g_scrV[o];
        float4 ii = g_scrI[o];
        ins3(vv.x, __float_as_int(ii.x), v0, v1, v2, i0, i1, i2);
        ins3(vv.y, __float_as_int(ii.y), v0, v1, v2, i0, i1, i2);
        ins3(vv.z, __float_as_int(ii.z), v0, v1, v2, i0, i1, i2);
    }

    const float* pu = pos_up + (size_t)(b * NUP + q) * 3;
    const float pux = pu[0], puy = pu[1], puz = pu[2];
    const float nu  = pux * pux + puy * puy + puz * puz;

    float w0 = 1.0f / (__fmaf_rn(2.0f, v0, nu) + 1e-6f);
    float w1 = 1.0f / (__fmaf_rn(2.0f, v1, nu) + 1e-6f);
    float w2 = 1.0f / (__fmaf_rn(2.0f, v2, nu) + 1e-6f);
    float inv = 1.0f / (w0 + w1 + w2);
    w0 *= inv; w1 *= inv; w2 *= inv;

    const float4* f0 = reinterpret_cast<const float4*>(feature + (size_t)(b * NPTS + i0) * C);
    const float4* f1 = reinterpret_cast<const float4*>(feature + (size_t)(b * NPTS + i1) * C);
    const float4* f2 = reinterpret_cast<const float4*>(feature + (size_t)(b * NPTS + i2) * C);

    const float4* sW4 = reinterpret_cast<const float4*>(sW);
    const float4* sb4 = reinterpret_cast<const float4*>(sb);

    float acc[64];
    #pragma unroll
    for (int m = 0; m < 16; ++m) {
        float4 bb = sb4[m];
        acc[4 * m + 0] = bb.x; acc[4 * m + 1] = bb.y;
        acc[4 * m + 2] = bb.z; acc[4 * m + 3] = bb.w;
    }

    #pragma unroll 4
    for (int c4 = 0; c4 < 16; ++c4) {
        float4 a = __ldg(f0 + c4);
        float4 e = __ldg(f1 + c4);
        float4 g = __ldg(f2 + c4);
        float nf[4];
        nf[0] = __fmaf_rn(w0, a.x, __fmaf_rn(w1, e.x, w2 * g.x));
        nf[1] = __fmaf_rn(w0, a.y, __fmaf_rn(w1, e.y, w2 * g.y));
        nf[2] = __fmaf_rn(w0, a.z, __fmaf_rn(w1, e.z, w2 * g.z));
        nf[3] = __fmaf_rn(w0, a.w, __fmaf_rn(w1, e.w, w2 * g.w));

        #pragma unroll
        for (int kk = 0; kk < 4; ++kk) {
            const float nfc = nf[kk];
            const float4* wr = sW4 + (size_t)(4 * c4 + kk) * 16;   // uniform LDS.128
            #pragma unroll
            for (int m = 0; m < 16; ++m) {
                float4 wv = wr[m];
                acc[4 * m + 0] = __fmaf_rn(nfc, wv.x, acc[4 * m + 0]);
                acc[4 * m + 1] = __fmaf_rn(nfc, wv.y, acc[4 * m + 1]);
                acc[4 * m + 2] = __fmaf_rn(nfc, wv.z, acc[4 * m + 2]);
                acc[4 * m + 3] = __fmaf_rn(nfc, wv.w, acc[4 * m + 3]);
            }
        }
    }

    float4* o4 = reinterpret_cast<float4*>(out + (size_t)(b * NUP + q) * C);
    #pragma unroll
    for (int m = 0; m < 16; ++m) {
        float4 v;
        v.x = fmaxf(acc[4 * m + 0], 0.0f);
        v.y = fmaxf(acc[4 * m + 1], 0.0f);
        v.z = fmaxf(acc[4 * m + 2], 0.0f);
        v.w = fmaxf(acc[4 * m + 3], 0.0f);
        o4[m] = v;
    }
}

extern "C" void kernel_launch(void* const* d_in, const int* in_sizes, int n_in,
                              void* d_out, int out_size)
{
    const float* feature = (const float*)d_in[0];
    const float* pos     = (const float*)d_in[1];
    const float* pos_up  = (const float*)d_in[2];
    const float* W       = (const float*)d_in[3];
    const float* bias    = (const float*)d_in[4];
    float* out = (float*)d_out;

    dim3 gridA(NUP / QTILE, S, BATCH);      // (64, 4, 4) = 1024 blocks
    knn_slice_kernel<<<gridA, TPB_A>>>(pos, pos_up);

    dim3 gridB(NUP / TPB_B, BATCH);         // (128, 4) = 512 blocks
    epilogue_kernel<<<gridB, TPB_B>>>(feature, pos_up, W, bias, out);
}

// round 11
// speedup vs baseline: 1.1982x; 1.0134x over previous
#include <cuda_runtime.h>
#include <math_constants.h>

static constexpr int NPTS  = 4096;
static constexpr int NUP   = 16384;
static constexpr int BATCH = 4;
static constexpr int C     = 64;

static constexpr int S      = 4;            // point slices (measured best)
static constexpr int SLICE  = NPTS / S;     // 1024 points
static constexpr int TPB_A  = 128;
static constexpr int QA     = 2;            // queries per thread (phase A)
static constexpr int QTILE  = TPB_A * QA;   // 256 queries per block

static constexpr int TPB_B  = 128;          // 4 warps = 4 d-groups
static constexpr int QBLK   = 128;          // queries per B block (4 per thread)
static constexpr int NFS    = 68;           // nf row stride (floats), padded
// dynamic smem: W[4096] + b[64] + snf[128*68]
static constexpr int SMEM_B = (C * C + C + QBLK * NFS) * 4;

// per-(slice, batch, query) top-3: values and indices (bitcast)
__device__ float4 g_scrV[S * BATCH * NUP];
__device__ float4 g_scrI[S * BATCH * NUP];

// ---- packed f32x2 helpers (Blackwell) ----
__device__ __forceinline__ unsigned long long pk2(float lo, float hi) {
    unsigned long long r;
    asm("mov.b64 %0, {%1, %2};" : "=l"(r) : "f"(lo), "f"(hi));
    return r;
}
__device__ __forceinline__ unsigned long long fma2(unsigned long long a,
                                                   unsigned long long b,
                                                   unsigned long long c) {
    unsigned long long d;
    asm("fma.rn.f32x2 %0, %1, %2, %3;" : "=l"(d) : "l"(a), "l"(b), "l"(c));
    return d;
}
__device__ __forceinline__ void unpk2(unsigned long long v, float& lo, float& hi) {
    asm("mov.b64 {%0, %1}, %2;" : "=f"(lo), "=f"(hi) : "l"(v));
}

// strict-< branchy insert: keeps earliest index on ties (jax.lax.top_k stability)
__device__ __forceinline__ void ins3(float v, int i,
                                     float& v0, float& v1, float& v2,
                                     int& i0, int& i1, int& i2) {
    if (v < v2) {
        if (v < v1) {
            v2 = v1; i2 = i1;
            if (v < v0) { v1 = v0; i1 = i0; v0 = v; i0 = i; }
            else        { v1 = v;  i1 = i; }
        } else { v2 = v; i2 = i; }
    }
}

// ============ Phase A: per-slice top-3, 2-pair batched inner loop ============
__global__ void __launch_bounds__(TPB_A, 8)
knn_slice_kernel(const float* __restrict__ pos,
                 const float* __restrict__ pos_up)
{
    // pair p: [2p] = {(x0,x1),(y0,y1)}, [2p+1] = {(z0,z1),(h0,h1)}
    __shared__ ulonglong2 spair[SLICE];

    const int s   = blockIdx.y;
    const int b   = blockIdx.z;
    const int tid = threadIdx.x;

    {
        const float* pb = pos + ((size_t)b * NPTS + (size_t)s * SLICE) * 3;
        for (int p = tid; p < SLICE / 2; p += TPB_A) {
            const float* s6 = pb + 6 * p;
            float x0 = s6[0], y0 = s6[1], z0 = s6[2];
            float x1 = s6[3], y1 = s6[4], z1 = s6[5];
            ulonglong2 A, B;
            A.x = pk2(x0, x1);
            A.y = pk2(y0, y1);
            B.x = pk2(z0, z1);
            B.y = pk2(0.5f * (x0 * x0 + y0 * y0 + z0 * z0),
                      0.5f * (x1 * x1 + y1 * y1 + z1 * z1));
            spair[2 * p + 0] = A;
            spair[2 * p + 1] = B;
        }
    }
    __syncthreads();

    const int qbase = blockIdx.x * QTILE + tid;

    unsigned long long nx[QA], ny[QA], nz[QA];
    #pragma unroll
    for (int k = 0; k < QA; ++k) {
        const int q = qbase + k * TPB_A;
        const float* pu = pos_up + (size_t)(b * NUP + q) * 3;
        float x = pu[0], y = pu[1], z = pu[2];
        nx[k] = pk2(-x, -x); ny[k] = pk2(-y, -y); nz[k] = pk2(-z, -z);
    }

    float v0[QA], v1[QA], v2[QA];
    int   i0[QA], i1[QA], i2[QA];
    #pragma unroll
    for (int k = 0; k < QA; ++k) {
        v0[k] = v1[k] = v2[k] = CUDART_INF_F;
        i0[k] = i1[k] = i2[k] = 0;
    }

    const int jbase = s * SLICE;

    // 2 pairs (4 points) per iteration: all loads + all distances hoisted
    // ahead of the gated insert region for MLP / latency hiding.
    #pragma unroll 2
    for (int pp = 0; pp < SLICE / 4; ++pp) {
        const int p0 = 2 * pp, p1 = 2 * pp + 1;
        ulonglong2 A0 = spair[2 * p0 + 0];
        ulonglong2 B0 = spair[2 * p0 + 1];
        ulonglong2 A1 = spair[2 * p1 + 0];
        ulonglong2 B1 = spair[2 * p1 + 1];

        unsigned long long sp0[QA], sp1[QA];
        #pragma unroll
        for (int k = 0; k < QA; ++k) {
            unsigned long long t0 = fma2(A0.x, nx[k], B0.y);
            t0 = fma2(A0.y, ny[k], t0);
            sp0[k] = fma2(B0.x, nz[k], t0);
            unsigned long long t1 = fma2(A1.x, nx[k], B1.y);
            t1 = fma2(A1.y, ny[k], t1);
            sp1[k] = fma2(B1.x, nz[k], t1);
        }

        #pragma unroll
        for (int k = 0; k < QA; ++k) {
            float s0, s1, s2, s3;
            unpk2(sp0[k], s0, s1);
            unpk2(sp1[k], s2, s3);
            if (fminf(s0, s1) < v2[k]) {
                ins3(s0, jbase + 2 * p0,     v0[k], v1[k], v2[k], i0[k], i1[k], i2[k]);
                ins3(s1, jbase + 2 * p0 + 1, v0[k], v1[k], v2[k], i0[k], i1[k], i2[k]);
            }
            if (fminf(s2, s3) < v2[k]) {
                ins3(s2, jbase + 2 * p1,     v0[k], v1[k], v2[k], i0[k], i1[k], i2[k]);
                ins3(s3, jbase + 2 * p1 + 1, v0[k], v1[k], v2[k], i0[k], i1[k], i2[k]);
            }
        }
    }

    #pragma unroll
    for (int k = 0; k < QA; ++k) {
        const int q = qbase + k * TPB_A;
        const size_t o = ((size_t)s * BATCH + b) * NUP + q;
        g_scrV[o] = make_float4(v0[k], v1[k], v2[k], 0.0f);
        g_scrI[o] = make_float4(__int_as_float(i0[k]), __int_as_float(i1[k]),
                                __int_as_float(i2[k]), 0.0f);
    }
}

// ====== Phase B: 4 queries x 16 outputs per thread, warp-uniform d-group =====
// Each W element loaded once per thread serves 4 query-FMAs -> 4x less W LDS.
// nf shared across d-warps via padded smem.
__global__ void __launch_bounds__(TPB_B, 4)
epilogue_kernel(const float* __restrict__ feature,
                const float* __restrict__ pos_up,
                const float* __restrict__ W,
                const float* __restrict__ bias,
                float* __restrict__ out)
{
    extern __shared__ float sm[];
    float* sW  = sm;                 // [4096]
    float* sb  = sm + C * C;         // [64]
    float* snf = sb + C;             // [QBLK * NFS]

    const int b    = blockIdx.y;
    const int tid  = threadIdx.x;
    const int w    = tid >> 5;        // d-group (warp-uniform): outputs [16w,16w+16)
    const int lane = tid & 31;

    // stage W + bias
    {
        const float4* Wg = reinterpret_cast<const float4*>(W);
        float4*       Ws = reinterpret_cast<float4*>(sW);
        #pragma unroll
        for (int i = tid; i < C * C / 4; i += TPB_B) Ws[i] = Wg[i];
        if (tid < C / 4)
            reinterpret_cast<float4*>(sb)[tid] = reinterpret_cast<const float4*>(bias)[tid];
    }
    __syncthreads();

    // ---- nf phase: this warp computes channels [16w,16w+16) for its 4 queries
    #pragma unroll
    for (int k = 0; k < 4; ++k) {
        const int qloc = k * 32 + lane;
        const int q    = blockIdx.x * QBLK + qloc;

        // merge S slice-top-3s (ascending slice order, strict <)
        float v0 = CUDART_INF_F, v1 = CUDART_INF_F, v2 = CUDART_INF_F;
        int   i0 = 0, i1 = 0, i2 = 0;
        #pragma unroll
        for (int s = 0; s < S; ++s) {
            const size_t o = ((size_t)s * BATCH + b) * NUP + q;
            float4 vv = g_scrV[o];
            float4 ii = g_scrI[o];
            ins3(vv.x, __float_as_int(ii.x), v0, v1, v2, i0, i1, i2);
            ins3(vv.y, __float_as_int(ii.y), v0, v1, v2, i0, i1, i2);
            ins3(vv.z, __float_as_int(ii.z), v0, v1, v2, i0, i1, i2);
        }

        const float* pu = pos_up + (size_t)(b * NUP + q) * 3;
        const float pux = pu[0], puy = pu[1], puz = pu[2];
        const float nu  = pux * pux + puy * puy + puz * puz;

        float w0 = 1.0f / (__fmaf_rn(2.0f, v0, nu) + 1e-6f);
        float w1 = 1.0f / (__fmaf_rn(2.0f, v1, nu) + 1e-6f);
        float w2 = 1.0f / (__fmaf_rn(2.0f, v2, nu) + 1e-6f);
        float inv = 1.0f / (w0 + w1 + w2);
        w0 *= inv; w1 *= inv; w2 *= inv;

        const float4* f0 = reinterpret_cast<const float4*>(feature + (size_t)(b * NPTS + i0) * C) + 4 * w;
        const float4* f1 = reinterpret_cast<const float4*>(feature + (size_t)(b * NPTS + i1) * C) + 4 * w;
        const float4* f2 = reinterpret_cast<const float4*>(feature + (size_t)(b * NPTS + i2) * C) + 4 * w;
        float4* dst = reinterpret_cast<float4*>(snf + qloc * NFS + 16 * w);
        #pragma unroll
        for (int i = 0; i < 4; ++i) {
            float4 a = __ldg(f0 + i);
            float4 e = __ldg(f1 + i);
            float4 g = __ldg(f2 + i);
            float4 nf;
            nf.x = __fmaf_rn(w0, a.x, __fmaf_rn(w1, e.x, w2 * g.x));
            nf.y = __fmaf_rn(w0, a.y, __fmaf_rn(w1, e.y, w2 * g.y));
            nf.z = __fmaf_rn(w0, a.z, __fmaf_rn(w1, e.z, w2 * g.z));
            nf.w = __fmaf_rn(w0, a.w, __fmaf_rn(w1, e.w, w2 * g.w));
            dst[i] = nf;
        }
    }
    __syncthreads();

    // ---- GEMM phase: 4 queries x 16 outputs; W loads broadcast & shared ----
    const float4* sW4 = reinterpret_cast<const float4*>(sW);
    const float4* sb4 = reinterpret_cast<const float4*>(sb);

    float acc[4][16];
    {
        float4 bb[4];
        #pragma unroll
        for (int m = 0; m < 4; ++m) bb[m] = sb4[4 * w + m];
        #pragma unroll
        for (int k = 0; k < 4; ++k)
            #pragma unroll
            for (int m = 0; m < 4; ++m) {
                acc[k][4 * m + 0] = bb[m].x;
                acc[k][4 * m + 1] = bb[m].y;
                acc[k][4 * m + 2] = bb[m].z;
                acc[k][4 * m + 3] = bb[m].w;
            }
    }

    #pragma unroll 2
    for (int c4 = 0; c4 < 16; ++c4) {
        // nf for the 4 queries, channels [4*c4, 4*c4+4)
        float4 nf[4];
        #pragma unroll
        for (int k = 0; k < 4; ++k)
            nf[k] = *reinterpret_cast<const float4*>(snf + (k * 32 + lane) * NFS + 4 * c4);

        #pragma unroll
        for (int kk = 0; kk < 4; ++kk) {
            const int c = 4 * c4 + kk;
            const float nfc[4] = { kk == 0 ? nf[0].x : kk == 1 ? nf[0].y : kk == 2 ? nf[0].z : nf[0].w,
                                   kk == 0 ? nf[1].x : kk == 1 ? nf[1].y : kk == 2 ? nf[1].z : nf[1].w,
                                   kk == 0 ? nf[2].x : kk == 1 ? nf[2].y : kk == 2 ? nf[2].z : nf[2].w,
                                   kk == 0 ? nf[3].x : kk == 1 ? nf[3].y : kk == 2 ? nf[3].z : nf[3].w };
            #pragma unroll
            for (int m = 0; m < 4; ++m) {
                float4 wv = sW4[(size_t)c * 16 + 4 * w + m];   // warp-uniform LDS.128
                #pragma unroll
                for (int k = 0; k < 4; ++k) {
                    acc[k][4 * m + 0] = __fmaf_rn(nfc[k], wv.x, acc[k][4 * m + 0]);
                    acc[k][4 * m + 1] = __fmaf_rn(nfc[k], wv.y, acc[k][4 * m + 1]);
                    acc[k][4 * m + 2] = __fmaf_rn(nfc[k], wv.z, acc[k][4 * m + 2]);
                    acc[k][4 * m + 3] = __fmaf_rn(nfc[k], wv.w, acc[k][4 * m + 3]);
                }
            }
        }
    }

    // ---- ReLU + store: each query's d-segment [16w,16w+16) ----
    #pragma unroll
    for (int k = 0; k < 4; ++k) {
        const int q = blockIdx.x * QBLK + k * 32 + lane;
        float4* o4 = reinterpret_cast<float4*>(out + (size_t)(b * NUP + q) * C + 16 * w);
        #pragma unroll
        for (int m = 0; m < 4; ++m) {
            float4 v;
            v.x = fmaxf(acc[k][4 * m + 0], 0.0f);
            v.y = fmaxf(acc[k][4 * m + 1], 0.0f);
            v.z = fmaxf(acc[k][4 * m + 2], 0.0f);
            v.w = fmaxf(acc[k][4 * m + 3], 0.0f);
            o4[m] = v;
        }
    }
}

extern "C" void kernel_launch(void* const* d_in, const int* in_sizes, int n_in,
                              void* d_out, int out_size)
{
    const float* feature = (const float*)d_in[0];
    const float* pos     = (const float*)d_in[1];
    const float* pos_up  = (const float*)d_in[2];
    const float* W       = (const float*)d_in[3];
    const float* bias    = (const float*)d_in[4];
    float* out = (float*)d_out;

    cudaFuncSetAttribute(epilogue_kernel, cudaFuncAttributeMaxDynamicSharedMemorySize, SMEM_B);

    dim3 gridA(NUP / QTILE, S, BATCH);      // (64, 4, 4) = 1024 blocks
    knn_slice_kernel<<<gridA, TPB_A>>>(pos, pos_up);

    dim3 gridB(NUP / QBLK, BATCH);          // (128, 4) = 512 blocks
    epilogue_kernel<<<gridB, TPB_B, SMEM_B>>>(feature, pos_up, W, bias, out);
}